// round 4
// baseline (speedup 1.0000x reference)
#include <cuda_runtime.h>
#include <cstdint>

#define N_NODES  4096
#define N_EDGES  16384
#define N_GRAPHS 128
#define DIM      64     // IN = H = 64 for all layers
#define EDIM     16
#define HD       4096   // DIM*DIM, edge-MLP width

// ---------------------------------------------------------------------------
// Scratch (static __device__ globals: no allocation anywhere)
// ---------------------------------------------------------------------------
__device__ float g_h[N_EDGES * HD];       // 268 MB: relu(ea@w1+b1), tf32-rounded
__device__ float g_theta[N_EDGES * HD];   // 268 MB: h@w2 + b2
__device__ float g_feat[2][N_NODES * DIM];
__device__ float g_agg[N_NODES * DIM];
__device__ float g_cnt[N_NODES];
__device__ float g_gcnt[N_GRAPHS];

__device__ __forceinline__ uint32_t f2tf32(float x) {
    uint32_t r;
    asm("cvt.rna.tf32.f32 %0, %1;" : "=r"(r) : "f"(x));
    return r;
}

// ---------------------------------------------------------------------------
// Utility: zero a float buffer
// ---------------------------------------------------------------------------
__global__ void zero_kernel(float* __restrict__ p, int n) {
    int i = blockIdx.x * blockDim.x + threadIdx.x;
    if (i < n) p[i] = 0.0f;
}

// In-degree counts (identical for all 3 layers)
__global__ void cnt_kernel(const int* __restrict__ ei) {
    int e = blockIdx.x * blockDim.x + threadIdx.x;
    if (e < N_EDGES) atomicAdd(&g_cnt[ei[N_EDGES + e]], 1.0f);
}

// ---------------------------------------------------------------------------
// h = relu(edge_attr @ w1 + b1), stored tf32-rounded.
// grid: (E/32, HD/128), block 256. Block tile: 32 edges x 128 cols.
// ---------------------------------------------------------------------------
__global__ void edge_mlp_kernel(const float* __restrict__ ea,
                                const float* __restrict__ w1,
                                const float* __restrict__ b1) {
    __shared__ float sa[32][20];    // row stride 80B: 16B-aligned float4 stores
    __shared__ float sw[16][128];
    const int e0 = blockIdx.x * 32;
    const int c0 = blockIdx.y * 128;
    const int t  = threadIdx.x;

    if (t < 128) {                         // 32 edges x 16 attrs
        int e = t >> 2, d4 = (t & 3) << 2;
        float4 v = *reinterpret_cast<const float4*>(ea + (e0 + e) * EDIM + d4);
        *reinterpret_cast<float4*>(&sa[e][d4]) = v;
    }
#pragma unroll
    for (int i = 0; i < 2; i++) {          // w1 slab 16 x 128
        int id = t + i * 256;
        int d = id >> 5, c4 = (id & 31) << 2;
        float4 v = *reinterpret_cast<const float4*>(w1 + d * HD + c0 + c4);
        *reinterpret_cast<float4*>(&sw[d][c4]) = v;
    }
    __syncthreads();

    const int lc = t & 127;                // column within tile
    const int eh = t >> 7;                 // 0/1 edge phase (constant per warp)
    float wreg[16];
#pragma unroll
    for (int d = 0; d < 16; d++) wreg[d] = sw[d][lc];
    const float bias = __ldg(b1 + c0 + lc);

#pragma unroll
    for (int j = 0; j < 16; j++) {
        int e = eh + j * 2;
        float acc = bias;
#pragma unroll
        for (int d = 0; d < 16; d++) acc += sa[e][d] * wreg[d];
        acc = fmaxf(acc, 0.0f);
        g_h[(size_t)(e0 + e) * HD + c0 + lc] = __uint_as_float(f2tf32(acc));
    }
}

// ---------------------------------------------------------------------------
// theta = g_h @ w2 + b2   [M=E=16384, N=HD=4096, K=HD=4096]
// TF32 mma.sync, BM=128 BN=256 BK=32, 2-stage cp.async pipeline, 256 thr.
// Warp grid 2x4, warp tile 64x64 (4 m-tiles x 8 n-tiles of m16n8k8).
// Smem strides: A=36 (banks 4g+q), B=264 (banks 8q+g) -> conflict-free.
// ---------------------------------------------------------------------------
#define BM 128
#define BN 256
#define BK 32
#define ASTRIDE 36
#define BSTRIDE 264
#define A_STAGE (BM * ASTRIDE)            // 4608 floats
#define B_STAGE (BK * BSTRIDE)            // 8448 floats
#define STAGE   (A_STAGE + B_STAGE)       // 13056 floats
#define SMEM_BYTES (2 * STAGE * 4)        // 104448 B

__global__ __launch_bounds__(256, 1)
void gemm_tf32_kernel(const float* __restrict__ Bw,   // w2 [K, N]
                      const float* __restrict__ b2) {
    extern __shared__ float smem[];
    const int t  = threadIdx.x;
    const int m0 = blockIdx.y * BM;
    const int n0 = blockIdx.x * BN;
    const int warp = t >> 5, lane = t & 31;
    const int wm = warp >> 2, wn = warp & 3;
    const int g = lane >> 2, q = lane & 3;

    const uint32_t sbase = (uint32_t)__cvta_generic_to_shared(smem);

    auto load_tile = [&](int kt, int s) {
        uint32_t ab = sbase + (uint32_t)(s * (STAGE * 4));
        uint32_t bb = ab + (uint32_t)(A_STAGE * 4);
        const float* Ag = g_h + (size_t)m0 * HD + kt * BK;
        const float* Bg = Bw + (size_t)(kt * BK) * HD + n0;
#pragma unroll
        for (int i = 0; i < 4; i++) {              // A tile: 128x32
            int id = t + i * 256;
            int row = id >> 3, c4 = (id & 7) << 2;
            asm volatile("cp.async.cg.shared.global [%0], [%1], 16;\n"
                :: "r"(ab + (uint32_t)((row * ASTRIDE + c4) * 4)),
                   "l"(Ag + (size_t)row * HD + c4));
        }
#pragma unroll
        for (int i = 0; i < 8; i++) {              // B tile: 32x256
            int id = t + i * 256;
            int row = id >> 6, c4 = (id & 63) << 2;
            asm volatile("cp.async.cg.shared.global [%0], [%1], 16;\n"
                :: "r"(bb + (uint32_t)((row * BSTRIDE + c4) * 4)),
                   "l"(Bg + (size_t)row * HD + c4));
        }
        asm volatile("cp.async.commit_group;\n" ::: "memory");
    };

    float acc[4][8][4];
#pragma unroll
    for (int mt = 0; mt < 4; mt++)
#pragma unroll
        for (int nt = 0; nt < 8; nt++)
#pragma unroll
            for (int r = 0; r < 4; r++) acc[mt][nt][r] = 0.0f;

    const int KT = HD / BK;   // 128
    load_tile(0, 0);

    for (int kt = 0; kt < KT; kt++) {
        asm volatile("cp.async.wait_group 0;\n" ::: "memory");
        __syncthreads();
        if (kt + 1 < KT) load_tile(kt + 1, (kt + 1) & 1);

        const float* a = smem + (kt & 1) * STAGE;
        const float* b = a + A_STAGE;

#pragma unroll
        for (int ks = 0; ks < 4; ks++) {
            const int k0 = ks * 8;
            uint32_t af[4][4];
#pragma unroll
            for (int mt = 0; mt < 4; mt++) {
                int r0 = wm * 64 + mt * 16 + g;
                af[mt][0] = __float_as_uint(a[r0 * ASTRIDE + k0 + q]);
                af[mt][1] = __float_as_uint(a[(r0 + 8) * ASTRIDE + k0 + q]);
                af[mt][2] = __float_as_uint(a[r0 * ASTRIDE + k0 + q + 4]);
                af[mt][3] = __float_as_uint(a[(r0 + 8) * ASTRIDE + k0 + q + 4]);
            }
            uint32_t bf[8][2];
#pragma unroll
            for (int nt = 0; nt < 8; nt++) {
                int c = wn * 64 + nt * 8 + g;
                bf[nt][0] = f2tf32(b[(k0 + q) * BSTRIDE + c]);
                bf[nt][1] = f2tf32(b[(k0 + q + 4) * BSTRIDE + c]);
            }
#pragma unroll
            for (int mt = 0; mt < 4; mt++)
#pragma unroll
                for (int nt = 0; nt < 8; nt++) {
                    asm volatile(
                        "mma.sync.aligned.m16n8k8.row.col.f32.tf32.tf32.f32 "
                        "{%0,%1,%2,%3}, {%4,%5,%6,%7}, {%8,%9}, {%0,%1,%2,%3};\n"
                        : "+f"(acc[mt][nt][0]), "+f"(acc[mt][nt][1]),
                          "+f"(acc[mt][nt][2]), "+f"(acc[mt][nt][3])
                        : "r"(af[mt][0]), "r"(af[mt][1]),
                          "r"(af[mt][2]), "r"(af[mt][3]),
                          "r"(bf[nt][0]), "r"(bf[nt][1]));
                }
        }
    }

    // epilogue: + b2, write theta
#pragma unroll
    for (int mt = 0; mt < 4; mt++) {
        int row = m0 + wm * 64 + mt * 16 + g;
#pragma unroll
        for (int nt = 0; nt < 8; nt++) {
            int col = n0 + wn * 64 + nt * 8 + q * 2;
            float ba = __ldg(b2 + col), bb2 = __ldg(b2 + col + 1);
            float2 v0 = make_float2(acc[mt][nt][0] + ba, acc[mt][nt][1] + bb2);
            float2 v1 = make_float2(acc[mt][nt][2] + ba, acc[mt][nt][3] + bb2);
            *reinterpret_cast<float2*>(&g_theta[(size_t)row * HD + col]) = v0;
            *reinterpret_cast<float2*>(&g_theta[(size_t)(row + 8) * HD + col]) = v1;
        }
    }
}

// ---------------------------------------------------------------------------
// msg[e,o] = sum_i x[src_e,i] * theta[e, i*64+o]; scatter-add into g_agg[dst]
// one warp per edge; theta reads fully coalesced; x broadcast via shfl.
// ---------------------------------------------------------------------------
__global__ void msg_kernel(const float* __restrict__ x,
                           const int* __restrict__ ei) {
    int e = (blockIdx.x * blockDim.x + threadIdx.x) >> 5;
    int lane = threadIdx.x & 31;
    if (e >= N_EDGES) return;
    int src = ei[e];
    int dst = ei[N_EDGES + e];
    float xv0 = x[src * DIM + lane];
    float xv1 = x[src * DIM + 32 + lane];
    const float* th = g_theta + (size_t)e * HD;
    float a0 = 0.0f, a1 = 0.0f;
#pragma unroll 8
    for (int i = 0; i < 32; i++) {
        float xi = __shfl_sync(0xffffffffu, xv0, i);
        a0 += xi * th[i * 64 + lane];
        a1 += xi * th[i * 64 + 32 + lane];
    }
#pragma unroll 8
    for (int i = 0; i < 32; i++) {
        float xi = __shfl_sync(0xffffffffu, xv1, i);
        a0 += xi * th[(32 + i) * 64 + lane];
        a1 += xi * th[(32 + i) * 64 + 32 + lane];
    }
    atomicAdd(&g_agg[dst * DIM + lane], a0);
    atomicAdd(&g_agg[dst * DIM + 32 + lane], a1);
}

// ---------------------------------------------------------------------------
// out[v] = relu(agg[v]/max(cnt,1) + x[v] @ root + bias); one warp per node
// ---------------------------------------------------------------------------
__global__ void node_update_kernel(const float* __restrict__ x,
                                   const float* __restrict__ root,
                                   const float* __restrict__ bias,
                                   float* __restrict__ out) {
    int v = (blockIdx.x * blockDim.x + threadIdx.x) >> 5;
    int lane = threadIdx.x & 31;
    if (v >= N_NODES) return;
    float inv = 1.0f / fmaxf(g_cnt[v], 1.0f);
    float a0 = g_agg[v * DIM + lane] * inv + __ldg(bias + lane);
    float a1 = g_agg[v * DIM + 32 + lane] * inv + __ldg(bias + 32 + lane);
    float xv0 = x[v * DIM + lane];
    float xv1 = x[v * DIM + 32 + lane];
#pragma unroll 8
    for (int i = 0; i < 32; i++) {
        float xi = __shfl_sync(0xffffffffu, xv0, i);
        a0 += xi * __ldg(root + i * 64 + lane);
        a1 += xi * __ldg(root + i * 64 + 32 + lane);
    }
#pragma unroll 8
    for (int i = 0; i < 32; i++) {
        float xi = __shfl_sync(0xffffffffu, xv1, i);
        a0 += xi * __ldg(root + (32 + i) * 64 + lane);
        a1 += xi * __ldg(root + (32 + i) * 64 + 32 + lane);
    }
    out[v * DIM + lane] = fmaxf(a0, 0.0f);
    out[v * DIM + 32 + lane] = fmaxf(a1, 0.0f);
}

// ---------------------------------------------------------------------------
// Global mean pool
// ---------------------------------------------------------------------------
__global__ void pool_sum_kernel(const float* __restrict__ y,
                                const int* __restrict__ batch,
                                float* __restrict__ out) {
    int v = (blockIdx.x * blockDim.x + threadIdx.x) >> 5;
    int lane = threadIdx.x & 31;
    if (v >= N_NODES) return;
    int gr = batch[v];
    atomicAdd(&out[gr * DIM + lane], y[v * DIM + lane]);
    atomicAdd(&out[gr * DIM + 32 + lane], y[v * DIM + 32 + lane]);
    if (lane == 0) atomicAdd(&g_gcnt[gr], 1.0f);
}

__global__ void pool_div_kernel(float* __restrict__ out) {
    int i = blockIdx.x * blockDim.x + threadIdx.x;
    if (i < N_GRAPHS * DIM) out[i] /= fmaxf(g_gcnt[i / DIM], 1.0f);
}

// ---------------------------------------------------------------------------
// Launch
// ---------------------------------------------------------------------------
extern "C" void kernel_launch(void* const* d_in, const int* in_sizes, int n_in,
                              void* d_out, int out_size) {
    (void)in_sizes; (void)n_in; (void)out_size;
    const float* x     = (const float*)d_in[0];
    const int*   ei    = (const int*)d_in[1];
    const float* ea    = (const float*)d_in[2];
    const int*   batch = (const int*)d_in[3];
    const float* W[3][6];
    for (int l = 0; l < 3; l++)
        for (int j = 0; j < 6; j++)
            W[l][j] = (const float*)d_in[4 + l * 6 + j];   // w1,b1,w2,b2,root,bias
    float* out = (float*)d_out;

    cudaFuncSetAttribute(gemm_tf32_kernel,
                         cudaFuncAttributeMaxDynamicSharedMemorySize, SMEM_BYTES);

    float *p_cnt, *p_agg, *p_feat, *p_gcnt;
    cudaGetSymbolAddress((void**)&p_cnt,  g_cnt);
    cudaGetSymbolAddress((void**)&p_agg,  g_agg);
    cudaGetSymbolAddress((void**)&p_feat, g_feat);
    cudaGetSymbolAddress((void**)&p_gcnt, g_gcnt);

    zero_kernel<<<(N_NODES + 255) / 256, 256>>>(p_cnt, N_NODES);
    cnt_kernel<<<(N_EDGES + 255) / 256, 256>>>(ei);

    const float* xin = x;
    for (int l = 0; l < 3; l++) {
        float* xout = p_feat + (l & 1) * (N_NODES * DIM);

        dim3 gmlp(N_EDGES / 32, HD / 128);
        edge_mlp_kernel<<<gmlp, 256>>>(ea, W[l][0], W[l][1]);

        dim3 gg(HD / BN, N_EDGES / BM);   // (16, 128)
        gemm_tf32_kernel<<<gg, 256, SMEM_BYTES>>>(W[l][2], W[l][3]);

        zero_kernel<<<(N_NODES * DIM + 255) / 256, 256>>>(p_agg, N_NODES * DIM);
        msg_kernel<<<N_EDGES / 8, 256>>>(xin, ei);
        node_update_kernel<<<N_NODES / 8, 256>>>(xin, W[l][4], W[l][5], xout);
        xin = xout;
    }

    zero_kernel<<<(N_GRAPHS * DIM + 255) / 256, 256>>>(out, N_GRAPHS * DIM);
    zero_kernel<<<1, 256>>>(p_gcnt, N_GRAPHS);
    pool_sum_kernel<<<N_NODES / 8, 256>>>(xin, batch, out);
    pool_div_kernel<<<(N_GRAPHS * DIM + 255) / 256, 256>>>(out);
}